// round 9
// baseline (speedup 1.0000x reference)
#include <cuda_runtime.h>
#include <cstdint>

#define N_ 64
#define C_ 64
#define T_ 300
#define V_ 25
#define F_ 64
#define TPB 5
#define M_ 125
#define MP 128
#define TV (T_ * V_)
#define XS_ST 68          // floats
#define WT2_ST 66         // float2 units, 72 rows (64 W + Wa1 + Wa2 + 6 zero)
#define HT2_ST 132        // float2 units, 64 rows, cols m 0..131
#define AT2_ST 32         // float2 units, 160 rows
#define ALPHA 0.2f
#define NEG_INF_ -9.0e15f

// float offsets
#define OFF_XS   0                    // xs 128x68 = 8704 (union with ht2)
#define OFF_HT2  0                    // 64*132*2 = 16896
#define OFF_R2   16896                // union{ WsT2 72*66*2=9504 , att2 160*32*2=10240 }
#define OFF_F1   27136                // 128
#define OFF_F2   27264                // 128
#define OFF_ADJ  27392                // 625 ints
#define SMEM_FLOATS 28020
#define SMEM_BYTES (SMEM_FLOATS * 4)  // 112080 B -> 2 CTAs/SM

__device__ __forceinline__ void split_tf32(float v, uint32_t& hi, uint32_t& lo) {
    uint32_t u = __float_as_uint(v) & 0xFFFFE000u;
    hi = u;
    lo = __float_as_uint(v - __uint_as_float(u));
}
__device__ __forceinline__ float2 split_f2(float v) {
    uint32_t h, l; split_tf32(v, h, l);
    return make_float2(__uint_as_float(h), __uint_as_float(l));
}
__device__ __forceinline__ float elu(float v) { return (v > 0.f) ? v : expm1f(v); }

#define MMA_TF32(d, a0, a1, a2, a3, b0, b1) \
    asm volatile("mma.sync.aligned.m16n8k8.row.col.f32.tf32.tf32.f32 " \
        "{%0,%1,%2,%3}, {%4,%5,%6,%7}, {%8,%9}, {%0,%1,%2,%3};" \
        : "+f"((d)[0]), "+f"((d)[1]), "+f"((d)[2]), "+f"((d)[3]) \
        : "r"(a0), "r"(a1), "r"(a2), "r"(a3), "r"(b0), "r"(b1))

__global__ void __launch_bounds__(256, 2) gat_kernel(
    const float* __restrict__ x,    // (N, C, T, V)
    const int*   __restrict__ adj,  // (V, V)
    const float* __restrict__ W,    // (C, F)
    const float* __restrict__ av,   // (2F, 1)
    float*       __restrict__ out)  // (N, F, T, V)
{
    extern __shared__ float sm[];
    float*  xs  = sm + OFF_XS;
    float2* ht2 = (float2*)(sm + OFF_HT2);
    float2* wt2 = (float2*)(sm + OFF_R2);
    float2* at2 = (float2*)(sm + OFF_R2);
    float*  f1s = sm + OFF_F1;
    float*  f2s = sm + OFF_F2;
    int*    adjs = (int*)(sm + OFF_ADJ);

    const int tid = threadIdx.x;
    const int w   = tid >> 5;
    const int l   = tid & 31;
    const int g   = l >> 2;
    const int qt  = l & 3;

    const int n  = blockIdx.x / (T_ / TPB);
    const int bt = blockIdx.x % (T_ / TPB);
    const int t0 = bt * TPB;
    const float* xn   = x   + (size_t)n * C_ * TV + (size_t)t0 * V_;
    float*       outn = out + (size_t)n * F_ * TV + (size_t)t0 * V_;

    // ---- staging: xs[m][c], WsT2 split, Wa1/Wa2, zero rows, adj ----
    for (int i = tid; i < MP * C_; i += 256) {
        const int c = i >> 7;
        const int m = i & 127;
        xs[m * XS_ST + c] = (m < M_) ? xn[c * TV + m] : 0.f;
    }
    for (int i = tid; i < C_ * F_; i += 256) {
        const int c = i >> 6;
        const int f = i & 63;
        wt2[f * WT2_ST + c] = split_f2(W[i]);
    }
    if (tid < C_) {
        const int c = tid;
        float s1 = 0.f, s2 = 0.f;
        #pragma unroll 16
        for (int f = 0; f < F_; ++f) {
            const float wv = W[c * F_ + f];
            s1 += wv * av[f];
            s2 += wv * av[F_ + f];
        }
        wt2[64 * WT2_ST + c] = split_f2(s1);
        wt2[65 * WT2_ST + c] = split_f2(s2);
    }
    for (int i = tid; i < 6 * WT2_ST; i += 256)
        wt2[66 * WT2_ST + i] = make_float2(0.f, 0.f);
    for (int i = tid; i < V_ * V_; i += 256) adjs[i] = adj[i];
    __syncthreads();

    // ---- GEMM1 (tensor): D[128][72] = x[128][64] @ [W | Wa1 | Wa2 | 0]^T ----
    float D[9][4];
    #pragma unroll
    for (int nt = 0; nt < 9; ++nt)
        #pragma unroll
        for (int q = 0; q < 4; ++q) D[nt][q] = 0.f;

    {
        const float* xr0 = &xs[(16 * w + g) * XS_ST];
        const float* xr8 = xr0 + 8 * XS_ST;
        #pragma unroll
        for (int ks = 0; ks < 8; ++ks) {
            const int kc = ks * 8 + qt;
            uint32_t ah[4], al[4];
            split_tf32(xr0[kc],     ah[0], al[0]);
            split_tf32(xr8[kc],     ah[1], al[1]);
            split_tf32(xr0[kc + 4], ah[2], al[2]);
            split_tf32(xr8[kc + 4], ah[3], al[3]);
            #pragma unroll
            for (int nt = 0; nt < 9; ++nt) {
                const float2 b0 = wt2[(nt * 8 + g) * WT2_ST + kc];
                const float2 b1 = wt2[(nt * 8 + g) * WT2_ST + kc + 4];
                MMA_TF32(D[nt], ah[0], ah[1], ah[2], ah[3],
                         __float_as_uint(b0.x), __float_as_uint(b1.x));
                MMA_TF32(D[nt], ah[0], ah[1], ah[2], ah[3],
                         __float_as_uint(b0.y), __float_as_uint(b1.y));
                MMA_TF32(D[nt], al[0], al[1], al[2], al[3],
                         __float_as_uint(b0.x), __float_as_uint(b1.x));
            }
        }
    }
    __syncthreads();   // all xs / wt2 reads complete before unions are overwritten

    // ---- write h^T split to ht2; f1/f2 from column 64/65; zero pads; zero att2 ----
    {
        const int m = 16 * w + g;
        #pragma unroll
        for (int nt = 0; nt < 8; ++nt) {
            const int c0 = nt * 8 + 2 * qt;
            ht2[c0 * HT2_ST + m]           = split_f2(D[nt][0]);
            ht2[(c0 + 1) * HT2_ST + m]     = split_f2(D[nt][1]);
            ht2[c0 * HT2_ST + m + 8]       = split_f2(D[nt][2]);
            ht2[(c0 + 1) * HT2_ST + m + 8] = split_f2(D[nt][3]);
        }
        if (qt == 0) {
            f1s[m] = D[8][0];  f2s[m] = D[8][1];
            f1s[m + 8] = D[8][2];  f2s[m + 8] = D[8][3];
        }
    }
    for (int i = tid; i < 160 * AT2_ST; i += 256) at2[i] = make_float2(0.f, 0.f);
    for (int i = tid; i < F_ * 4; i += 256)
        ht2[(i >> 2) * HT2_ST + 128 + (i & 3)] = make_float2(0.f, 0.f);
    __syncthreads();

    // ---- masked leaky-relu + softmax; write att split to padded rows ----
    if (tid < 160) {
        const int r = tid;
        const int v = r & 31;
        if (v < V_) {
            const int gg = r >> 5;
            const int base = gg * V_;
            const float fi = f1s[base + v];
            float e[V_];
            float mx = NEG_INF_;
            #pragma unroll
            for (int j = 0; j < V_; ++j) {
                float val = fi + f2s[base + j];
                val = (val > 0.f) ? val : ALPHA * val;
                val = (adjs[v * V_ + j] > 0) ? val : NEG_INF_;
                e[j] = val;
                mx = fmaxf(mx, val);
            }
            float s = 0.f;
            #pragma unroll
            for (int j = 0; j < V_; ++j) { const float p = __expf(e[j] - mx); e[j] = p; s += p; }
            const float inv = 1.f / s;
            #pragma unroll
            for (int j = 0; j < V_; ++j) at2[r * AT2_ST + j] = split_f2(e[j] * inv);
        }
    }
    __syncthreads();

    // ---- GEMM2 (tensor): per 16-row strip, D2 = att[16][32] @ h[32][64] ----
    const int nstrips = (w < 2) ? 2 : 1;
    for (int pass = 0; pass < nstrips; ++pass) {
        const int s = (pass == 0) ? w : (8 + w);
        const int base = V_ * (s >> 1);
        float D2[8][4];
        #pragma unroll
        for (int nt = 0; nt < 8; ++nt)
            #pragma unroll
            for (int q = 0; q < 4; ++q) D2[nt][q] = 0.f;

        const int ra = 16 * s + g;
        #pragma unroll
        for (int ks = 0; ks < 4; ++ks) {
            const int k0 = ks * 8 + qt;
            const float2 A0 = at2[ra * AT2_ST + k0];
            const float2 A1 = at2[(ra + 8) * AT2_ST + k0];
            const float2 A2 = at2[ra * AT2_ST + k0 + 4];
            const float2 A3 = at2[(ra + 8) * AT2_ST + k0 + 4];
            const uint32_t ah0 = __float_as_uint(A0.x), ah1 = __float_as_uint(A1.x);
            const uint32_t ah2 = __float_as_uint(A2.x), ah3 = __float_as_uint(A3.x);
            const uint32_t al0 = __float_as_uint(A0.y), al1 = __float_as_uint(A1.y);
            const uint32_t al2 = __float_as_uint(A2.y), al3 = __float_as_uint(A3.y);
            #pragma unroll
            for (int nt = 0; nt < 8; ++nt) {
                const float2 b0 = ht2[(nt * 8 + g) * HT2_ST + base + k0];
                const float2 b1 = ht2[(nt * 8 + g) * HT2_ST + base + k0 + 4];
                MMA_TF32(D2[nt], ah0, ah1, ah2, ah3,
                         __float_as_uint(b0.x), __float_as_uint(b1.x));
                MMA_TF32(D2[nt], ah0, ah1, ah2, ah3,
                         __float_as_uint(b0.y), __float_as_uint(b1.y));
                MMA_TF32(D2[nt], al0, al1, al2, al3,
                         __float_as_uint(b0.x), __float_as_uint(b1.x));
            }
        }

        // ---- epilogue: ELU + direct coalesced-sector STG ----
        const int v0 = ra & 31;
        const int v1 = (ra + 8) & 31;
        const int mr0 = base + v0;
        const int mr1 = base + v1;
        const bool st0 = (v0 < V_);
        const bool st1 = (v1 < V_);
        #pragma unroll
        for (int nt = 0; nt < 8; ++nt) {
            const int c0 = nt * 8 + 2 * qt;
            if (st0) {
                outn[c0 * TV + mr0]       = elu(D2[nt][0]);
                outn[(c0 + 1) * TV + mr0] = elu(D2[nt][1]);
            }
            if (st1) {
                outn[c0 * TV + mr1]       = elu(D2[nt][2]);
                outn[(c0 + 1) * TV + mr1] = elu(D2[nt][3]);
            }
        }
    }
}

extern "C" void kernel_launch(void* const* d_in, const int* in_sizes, int n_in,
                              void* d_out, int out_size)
{
    const float* x   = (const float*)d_in[0];
    const int*   adj = (const int*)  d_in[1];
    const float* W   = (const float*)d_in[2];
    const float* a   = (const float*)d_in[3];
    float* out = (float*)d_out;

    cudaFuncSetAttribute(gat_kernel, cudaFuncAttributeMaxDynamicSharedMemorySize, SMEM_BYTES);
    dim3 grid(N_ * (T_ / TPB));
    gat_kernel<<<grid, 256, SMEM_BYTES>>>(x, adj, W, a, out);
}

// round 10
// speedup vs baseline: 1.0498x; 1.0498x over previous
#include <cuda_runtime.h>
#include <cstdint>

#define N_ 64
#define C_ 64
#define T_ 300
#define V_ 25
#define F_ 64
#define TPB 5
#define M_ 125
#define MP 128
#define TV (T_ * V_)
#define XS_ST 68
#define WT2_ST 66          // float2 units per row; 72 rows (64 W + Wa1 + Wa2 + 6 zero)
#define HS_STRIDE 68
#define ATT_STRIDE 28
#define OS_STRIDE 67
#define ALPHA 0.2f
#define NEG_INF_ -9.0e15f

// ---- smem float offsets ----
#define OFF_XS   0                     // xs[m][c] 128x68 = 8704 ; union: hs[m][f]
#define OFF_WT2  8704                  // 72*66 float2 = 9504 floats ; union: out staging (8375)
#define OFF_ATT  18208                 // 128*28 = 3584
#define OFF_F1   21792                 // 128
#define OFF_F2   21920                 // 128
#define OFF_ADJ  22048                 // 625 ints
#define SMEM_FLOATS 22673
#define SMEM_BYTES (SMEM_FLOATS * 4)   // 90692 B -> 2 CTAs/SM

__device__ __forceinline__ void split_tf32(float v, uint32_t& hi, uint32_t& lo) {
    uint32_t u = __float_as_uint(v) & 0xFFFFE000u;
    hi = u;
    lo = __float_as_uint(v - __uint_as_float(u));
}
__device__ __forceinline__ float2 split_f2(float v) {
    uint32_t h, l; split_tf32(v, h, l);
    return make_float2(__uint_as_float(h), __uint_as_float(l));
}

#define MMA_TF32(d, a, b0, b1) \
    asm volatile("mma.sync.aligned.m16n8k8.row.col.f32.tf32.tf32.f32 " \
        "{%0,%1,%2,%3}, {%4,%5,%6,%7}, {%8,%9}, {%0,%1,%2,%3};" \
        : "+f"((d)[0]), "+f"((d)[1]), "+f"((d)[2]), "+f"((d)[3]) \
        : "r"((a)[0]), "r"((a)[1]), "r"((a)[2]), "r"((a)[3]), "r"(b0), "r"(b1))

__global__ void __launch_bounds__(256, 2) gat_kernel(
    const float* __restrict__ x,    // (N, C, T, V)
    const int*   __restrict__ adj,  // (V, V)
    const float* __restrict__ W,    // (C, F)
    const float* __restrict__ av,   // (2F, 1)
    float*       __restrict__ out)  // (N, F, T, V)
{
    extern __shared__ float sm[];
    float*  xs   = sm + OFF_XS;
    float*  hs   = sm + OFF_XS;          // union (xs dead after GEMM1)
    float2* wt2  = (float2*)(sm + OFF_WT2);
    float*  os   = sm + OFF_WT2;         // union (wt2 dead after GEMM1)
    float*  attm = sm + OFF_ATT;
    float*  f1s  = sm + OFF_F1;
    float*  f2s  = sm + OFF_F2;
    int*    adjs = (int*)(sm + OFF_ADJ);

    const int tid = threadIdx.x;
    const int w   = tid >> 5;
    const int l   = tid & 31;
    const int g   = l >> 2;
    const int qt  = l & 3;
    const int tf  = tid & 15;       // GEMM2: f0 = 4*tf
    const int tm  = tid >> 4;       // GEMM2: m0 = 8*tm
    const int f0  = tf << 2;
    const int m0  = tm << 3;

    const int n  = blockIdx.x / (T_ / TPB);
    const int bt = blockIdx.x % (T_ / TPB);
    const int t0 = bt * TPB;
    const float* xn   = x   + (size_t)n * C_ * TV + (size_t)t0 * V_;
    float*       outn = out + (size_t)n * F_ * TV + (size_t)t0 * V_;

    // ---- staging ----
    for (int i = tid; i < MP * C_; i += 256) {
        const int c = i >> 7;
        const int m = i & 127;
        xs[m * XS_ST + c] = (m < M_) ? xn[c * TV + m] : 0.f;
    }
    for (int i = tid; i < C_ * F_; i += 256) {
        const int c = i >> 6;
        const int f = i & 63;
        wt2[f * WT2_ST + c] = split_f2(W[i]);     // presplit B once
    }
    if (tid < C_) {                                // Wa1 / Wa2 columns (f1/f2 fold)
        const int c = tid;
        float s1 = 0.f, s2 = 0.f;
        #pragma unroll 16
        for (int f = 0; f < F_; ++f) {
            const float wv = W[c * F_ + f];
            s1 += wv * av[f];
            s2 += wv * av[F_ + f];
        }
        wt2[64 * WT2_ST + c] = split_f2(s1);
        wt2[65 * WT2_ST + c] = split_f2(s2);
    }
    for (int i = tid; i < 6 * WT2_ST; i += 256)
        wt2[66 * WT2_ST + i] = make_float2(0.f, 0.f);
    for (int i = tid; i < V_ * V_; i += 256) adjs[i] = adj[i];
    for (int i = tid; i < MP * ATT_STRIDE; i += 256) attm[i] = 0.f;
    __syncthreads();

    // ---- GEMM1 (tensor): D[128][72] = x @ [W | Wa1 | Wa2 | 0]^T, tf32 3-term ----
    float D[9][4];
    #pragma unroll
    for (int nt = 0; nt < 9; ++nt)
        #pragma unroll
        for (int q = 0; q < 4; ++q) D[nt][q] = 0.f;

    {
        const float* xr0 = &xs[(16 * w + g) * XS_ST];
        const float* xr8 = xr0 + 8 * XS_ST;
        #pragma unroll
        for (int ks = 0; ks < 8; ++ks) {
            const int kc = ks * 8 + qt;
            uint32_t ah[4], al[4];
            split_tf32(xr0[kc],     ah[0], al[0]);
            split_tf32(xr8[kc],     ah[1], al[1]);
            split_tf32(xr0[kc + 4], ah[2], al[2]);
            split_tf32(xr8[kc + 4], ah[3], al[3]);
            #pragma unroll
            for (int nt = 0; nt < 9; ++nt) {
                const float2 b0 = wt2[(nt * 8 + g) * WT2_ST + kc];
                const float2 b1 = wt2[(nt * 8 + g) * WT2_ST + kc + 4];
                const uint32_t bh0 = __float_as_uint(b0.x), bl0 = __float_as_uint(b0.y);
                const uint32_t bh1 = __float_as_uint(b1.x), bl1 = __float_as_uint(b1.y);
                MMA_TF32(D[nt], ah, bh0, bh1);
                MMA_TF32(D[nt], ah, bl0, bl1);
                MMA_TF32(D[nt], al, bh0, bh1);
            }
        }
    }
    __syncthreads();   // xs + wt2 reads complete before union overwrite

    // ---- write hs (overlay on xs) + f1/f2 from fold columns ----
    {
        const int m = 16 * w + g;
        #pragma unroll
        for (int nt = 0; nt < 8; ++nt) {
            const int cc = nt * 8 + 2 * qt;
            *(float2*)&hs[m * HS_STRIDE + cc]       = make_float2(D[nt][0], D[nt][1]);
            *(float2*)&hs[(m + 8) * HS_STRIDE + cc] = make_float2(D[nt][2], D[nt][3]);
        }
        if (qt == 0) {
            f1s[m]     = D[8][0];  f2s[m]     = D[8][1];
            f1s[m + 8] = D[8][2];  f2s[m + 8] = D[8][3];
        }
    }
    __syncthreads();

    // ---- masked leaky-relu + row softmax ----
    if (tid < M_) {
        const int m = tid;
        const int gg = m / V_;
        const int i  = m - gg * V_;
        const int base = gg * V_;
        const float fi = f1s[m];
        float e[V_];
        float mx = NEG_INF_;
        #pragma unroll
        for (int j = 0; j < V_; ++j) {
            float v = fi + f2s[base + j];
            v = (v > 0.f) ? v : ALPHA * v;
            v = (adjs[i * V_ + j] > 0) ? v : NEG_INF_;
            e[j] = v;
            mx = fmaxf(mx, v);
        }
        float s = 0.f;
        #pragma unroll
        for (int j = 0; j < V_; ++j) { const float p = __expf(e[j] - mx); e[j] = p; s += p; }
        const float inv = 1.f / s;
        #pragma unroll
        for (int j = 0; j < V_; ++j) attm[m * ATT_STRIDE + j] = e[j] * inv;
    }
    __syncthreads();

    // ---- GEMM2 (SIMT, R2/R8-proven) ----
    float o[8][4];
    #pragma unroll
    for (int k = 0; k < 8; ++k)
        #pragma unroll
        for (int ff = 0; ff < 4; ++ff) o[k][ff] = 0.f;

    const int baseA = (m0 / V_) * V_;
    int baseB = ((m0 + 7) / V_) * V_;
    if (baseB > 100) baseB = 100;
    const int splitK = baseA + V_;

    #pragma unroll
    for (int jb = 0; jb < ATT_STRIDE; jb += 4) {
        float4 hA[4], hB[4];
        #pragma unroll
        for (int jj = 0; jj < 4; ++jj) {
            hA[jj] = *(const float4*)&hs[(baseA + jb + jj) * HS_STRIDE + f0];
            hB[jj] = *(const float4*)&hs[(baseB + jb + jj) * HS_STRIDE + f0];
        }
        #pragma unroll
        for (int k = 0; k < 8; ++k) {
            const float4 avv = *(const float4*)&attm[(m0 + k) * ATT_STRIDE + jb];
            const float4* h = (m0 + k >= splitK) ? hB : hA;
            o[k][0] += avv.x * h[0].x + avv.y * h[1].x + avv.z * h[2].x + avv.w * h[3].x;
            o[k][1] += avv.x * h[0].y + avv.y * h[1].y + avv.z * h[2].y + avv.w * h[3].y;
            o[k][2] += avv.x * h[0].z + avv.y * h[1].z + avv.z * h[2].z + avv.w * h[3].z;
            o[k][3] += avv.x * h[0].w + avv.y * h[1].w + avv.z * h[2].w + avv.w * h[3].w;
        }
    }

    // ---- ELU + stage transposed into wt2 region (dead post-GEMM1) ----
    #pragma unroll
    for (int k = 0; k < 8; ++k) {
        const int m = m0 + k;
        if (m < M_) {
            #pragma unroll
            for (int ff = 0; ff < 4; ++ff) {
                float v = o[k][ff];
                v = (v > 0.f) ? v : expm1f(v);
                os[m * OS_STRIDE + f0 + ff] = v;
            }
        }
    }
    __syncthreads();

    // ---- store: out[n][f][t0*25 + m], 125 contiguous per f ----
    for (int f = w; f < F_; f += 8) {
        for (int mm = l; mm < M_; mm += 32)
            outn[f * TV + mm] = os[mm * OS_STRIDE + f];
    }
}

extern "C" void kernel_launch(void* const* d_in, const int* in_sizes, int n_in,
                              void* d_out, int out_size)
{
    const float* x   = (const float*)d_in[0];
    const int*   adj = (const int*)  d_in[1];
    const float* W   = (const float*)d_in[2];
    const float* a   = (const float*)d_in[3];
    float* out = (float*)d_out;

    cudaFuncSetAttribute(gat_kernel, cudaFuncAttributeMaxDynamicSharedMemorySize, SMEM_BYTES);
    dim3 grid(N_ * (T_ / TPB));
    gat_kernel<<<grid, 256, SMEM_BYTES>>>(x, adj, W, a, out);
}

// round 11
// speedup vs baseline: 1.4474x; 1.3787x over previous
#include <cuda_runtime.h>
#include <cstdint>

#define N_ 64
#define C_ 64
#define T_ 300
#define V_ 25
#define F_ 64
#define TPB 5
#define M_ 125
#define TV (T_ * V_)
#define WT_ST 68            // conflict-free B loads in GEMM1 (4g+qt)
#define HS_ST 72            // conflict-free B loads in GEMM2 (8qt+g)
#define AT_ST 36            // conflict-free A loads in GEMM2 (4g+qt)
#define OS_ST 67            // conflict-free column read at final store (3m)
#define ALPHA 0.2f
#define NEG_INF_ -9.0e15f

// ---- smem float offsets ----
#define OFF_OS  0           // os[125][67] = 8375 ; union with WT (WT dead after GEMM1)
#define OFF_WT  0           // WsT[72][68] = 4896 (64 W rows + Wa1 + Wa2 + 6 zero)
#define OFF_HS  8376        // hs[132][72] = 9504 (rows 125-127 zero via A-guard, 128-131 zeroed)
#define OFF_ATT 17880       // attm[160][36] = 5760 (padded-row layout, zero-inited)
#define OFF_F1  23640       // 128
#define OFF_F2  23768       // 128
#define OFF_ADJ 23896       // 625 ints
#define SMEM_FLOATS 24521
#define SMEM_BYTES (SMEM_FLOATS * 4)   // 98084 B -> 2 CTAs/SM

__device__ __forceinline__ void split_tf32(float v, uint32_t& hi, uint32_t& lo) {
    uint32_t u = __float_as_uint(v) & 0xFFFFE000u;
    hi = u;
    lo = __float_as_uint(v - __uint_as_float(u));
}
__device__ __forceinline__ float elu(float v) { return (v > 0.f) ? v : expm1f(v); }

#define MMA_TF32(d, a, b0, b1) \
    asm volatile("mma.sync.aligned.m16n8k8.row.col.f32.tf32.tf32.f32 " \
        "{%0,%1,%2,%3}, {%4,%5,%6,%7}, {%8,%9}, {%0,%1,%2,%3};" \
        : "+f"((d)[0]), "+f"((d)[1]), "+f"((d)[2]), "+f"((d)[3]) \
        : "r"((a)[0]), "r"((a)[1]), "r"((a)[2]), "r"((a)[3]), "r"(b0), "r"(b1))

__global__ void __launch_bounds__(256, 2) gat_kernel(
    const float* __restrict__ x,    // (N, C, T, V)
    const int*   __restrict__ adj,  // (V, V)
    const float* __restrict__ W,    // (C, F)
    const float* __restrict__ av,   // (2F, 1)
    float*       __restrict__ out)  // (N, F, T, V)
{
    extern __shared__ float sm[];
    float* os   = sm + OFF_OS;
    float* WsT  = sm + OFF_WT;
    float* hs   = sm + OFF_HS;
    float* attm = sm + OFF_ATT;
    float* f1s  = sm + OFF_F1;
    float* f2s  = sm + OFF_F2;
    int*   adjs = (int*)(sm + OFF_ADJ);

    const int tid = threadIdx.x;
    const int w   = tid >> 5;
    const int l   = tid & 31;
    const int g   = l >> 2;
    const int qt  = l & 3;

    const int n  = blockIdx.x / (T_ / TPB);
    const int bt = blockIdx.x % (T_ / TPB);
    const int t0 = bt * TPB;
    const float* xn   = x   + (size_t)n * C_ * TV + (size_t)t0 * V_;
    float*       outn = out + (size_t)n * F_ * TV + (size_t)t0 * V_;

    // ---- A-fragment gmem loads FIRST (independent of smem; overlap staging) ----
    const int mA0 = 16 * w + g;          // always < 120
    const bool vA1 = (mA0 + 8) < M_;     // guard rows 125..127 (OOB on last CTA)
    float Ax[8][4];
    #pragma unroll
    for (int ks = 0; ks < 8; ++ks) {
        const int c0 = 8 * ks + qt;
        Ax[ks][0] = xn[c0 * TV + mA0];
        Ax[ks][1] = vA1 ? xn[c0 * TV + mA0 + 8] : 0.f;
        Ax[ks][2] = xn[(c0 + 4) * TV + mA0];
        Ax[ks][3] = vA1 ? xn[(c0 + 4) * TV + mA0 + 8] : 0.f;
    }

    // ---- staging: WsT, Wa1/Wa2 fold columns, zero rows, att zero, hs pad, adj ----
    for (int i = tid; i < C_ * F_; i += 256) {
        const int c = i >> 6;
        const int f = i & 63;
        WsT[f * WT_ST + c] = W[i];
    }
    {   // Wa1[c] = sum_f W[c][f]*a1[f]; balanced: 64 c x 4 quads of 16 f
        const int c = tid >> 2;
        const int q = tid & 3;
        const float* wr = W + c * F_ + q * 16;
        const float* a1 = av + q * 16;
        const float* a2 = av + F_ + q * 16;
        float s1 = 0.f, s2 = 0.f;
        #pragma unroll
        for (int f = 0; f < 16; ++f) {
            const float wv = wr[f];
            s1 += wv * a1[f];
            s2 += wv * a2[f];
        }
        s1 += __shfl_xor_sync(0xffffffffu, s1, 1);
        s1 += __shfl_xor_sync(0xffffffffu, s1, 2);
        s2 += __shfl_xor_sync(0xffffffffu, s2, 1);
        s2 += __shfl_xor_sync(0xffffffffu, s2, 2);
        if (q == 0) {
            WsT[64 * WT_ST + c] = s1;
            WsT[65 * WT_ST + c] = s2;
        }
    }
    for (int i = tid; i < 6 * WT_ST; i += 256) WsT[66 * WT_ST + i] = 0.f;   // B rows 66-71
    for (int i = tid; i < 160 * AT_ST; i += 256) attm[i] = 0.f;
    for (int i = tid; i < 4 * HS_ST; i += 256) hs[128 * HS_ST + i] = 0.f;   // h rows 128-131
    for (int i = tid; i < V_ * V_; i += 256) adjs[i] = adj[i];
    __syncthreads();

    // ---- GEMM1 (tensor): D[128][72] = x[128][64] @ [W | Wa1 | Wa2 | 0]^T ----
    float D[9][4];
    #pragma unroll
    for (int nt = 0; nt < 9; ++nt)
        #pragma unroll
        for (int q = 0; q < 4; ++q) D[nt][q] = 0.f;

    #pragma unroll
    for (int ks = 0; ks < 8; ++ks) {
        const int kc = 8 * ks + qt;
        uint32_t ah[4], al[4];
        split_tf32(Ax[ks][0], ah[0], al[0]);
        split_tf32(Ax[ks][1], ah[1], al[1]);
        split_tf32(Ax[ks][2], ah[2], al[2]);
        split_tf32(Ax[ks][3], ah[3], al[3]);
        #pragma unroll
        for (int nt = 0; nt < 9; ++nt) {
            uint32_t bh0, bl0, bh1, bl1;
            split_tf32(WsT[(nt * 8 + g) * WT_ST + kc],     bh0, bl0);
            split_tf32(WsT[(nt * 8 + g) * WT_ST + kc + 4], bh1, bl1);
            MMA_TF32(D[nt], ah, bh0, bh1);
            MMA_TF32(D[nt], ah, bl0, bl1);
            MMA_TF32(D[nt], al, bh0, bh1);
        }
    }

    // ---- write hs + f1/f2 from fold columns ----
    {
        const int m = 16 * w + g;
        #pragma unroll
        for (int nt = 0; nt < 8; ++nt) {
            const int cc = nt * 8 + 2 * qt;
            *(float2*)&hs[m * HS_ST + cc]       = make_float2(D[nt][0], D[nt][1]);
            *(float2*)&hs[(m + 8) * HS_ST + cc] = make_float2(D[nt][2], D[nt][3]);
        }
        if (qt == 0) {
            f1s[m]     = D[8][0];  f2s[m]     = D[8][1];
            f1s[m + 8] = D[8][2];  f2s[m + 8] = D[8][3];
        }
    }
    __syncthreads();

    // ---- masked leaky-relu + softmax -> attm in PADDED-ROW layout (32/group) ----
    if (tid < 160) {
        const int v = tid & 31;
        if (v < V_) {
            const int gg = tid >> 5;
            const int base = gg * V_;
            const float fi = f1s[base + v];
            float e[V_];
            float mx = NEG_INF_;
            #pragma unroll
            for (int j = 0; j < V_; ++j) {
                float val = fi + f2s[base + j];
                val = (val > 0.f) ? val : ALPHA * val;
                val = (adjs[v * V_ + j] > 0) ? val : NEG_INF_;
                e[j] = val;
                mx = fmaxf(mx, val);
            }
            float s = 0.f;
            #pragma unroll
            for (int j = 0; j < V_; ++j) { const float p = __expf(e[j] - mx); e[j] = p; s += p; }
            const float inv = 1.f / s;
            #pragma unroll
            for (int j = 0; j < V_; ++j) attm[tid * AT_ST + j] = e[j] * inv;
        }
    }
    __syncthreads();

    // ---- GEMM2 (tensor): strip s (16 padded rows) x h[32][64]; 10 strips / 8 warps ----
    const int nstrips = (w < 2) ? 2 : 1;
    for (int pass = 0; pass < nstrips; ++pass) {
        const int s = (pass == 0) ? w : (8 + w);
        const int base = V_ * (s >> 1);
        const int ra = 16 * s + g;

        float D2[8][4];
        #pragma unroll
        for (int nt = 0; nt < 8; ++nt)
            #pragma unroll
            for (int q = 0; q < 4; ++q) D2[nt][q] = 0.f;

        #pragma unroll
        for (int ks = 0; ks < 4; ++ks) {
            const int k0 = 8 * ks + qt;
            uint32_t ah[4], al[4];
            split_tf32(attm[ra * AT_ST + k0],           ah[0], al[0]);
            split_tf32(attm[(ra + 8) * AT_ST + k0],     ah[1], al[1]);
            split_tf32(attm[ra * AT_ST + k0 + 4],       ah[2], al[2]);
            split_tf32(attm[(ra + 8) * AT_ST + k0 + 4], ah[3], al[3]);
            #pragma unroll
            for (int nt = 0; nt < 8; ++nt) {
                uint32_t bh0, bl0, bh1, bl1;
                split_tf32(hs[(base + k0) * HS_ST + 8 * nt + g],     bh0, bl0);
                split_tf32(hs[(base + k0 + 4) * HS_ST + 8 * nt + g], bh1, bl1);
                MMA_TF32(D2[nt], ah, bh0, bh1);
                MMA_TF32(D2[nt], ah, bl0, bl1);
                MMA_TF32(D2[nt], al, bh0, bh1);
            }
        }

        // ---- ELU + stage to os (union with dead WT region) ----
        const int v0 = ra & 31;
        const int v1 = (ra + 8) & 31;
        const int m0r = base + v0;
        const int m1r = base + v1;
        const bool st1 = (v1 < V_);     // v0 < 25 always (v0 <= 23)
        #pragma unroll
        for (int nt = 0; nt < 8; ++nt) {
            const int cc = nt * 8 + 2 * qt;
            os[m0r * OS_ST + cc]     = elu(D2[nt][0]);
            os[m0r * OS_ST + cc + 1] = elu(D2[nt][1]);
            if (st1) {
                os[m1r * OS_ST + cc]     = elu(D2[nt][2]);
                os[m1r * OS_ST + cc + 1] = elu(D2[nt][3]);
            }
        }
    }
    __syncthreads();

    // ---- store: out[n][f][t0*25 + m], 125 contiguous floats per f ----
    for (int f = w; f < F_; f += 8) {
        for (int mm = l; mm < M_; mm += 32)
            outn[f * TV + mm] = os[mm * OS_ST + f];
    }
}

extern "C" void kernel_launch(void* const* d_in, const int* in_sizes, int n_in,
                              void* d_out, int out_size)
{
    const float* x   = (const float*)d_in[0];
    const int*   adj = (const int*)  d_in[1];
    const float* W   = (const float*)d_in[2];
    const float* a   = (const float*)d_in[3];
    float* out = (float*)d_out;

    cudaFuncSetAttribute(gat_kernel, cudaFuncAttributeMaxDynamicSharedMemorySize, SMEM_BYTES);
    dim3 grid(N_ * (T_ / TPB));
    gat_kernel<<<grid, 256, SMEM_BYTES>>>(x, adj, W, a, out);
}

// round 12
// speedup vs baseline: 2.1023x; 1.4525x over previous
#include <cuda_runtime.h>
#include <cstdint>

#define N_ 64
#define C_ 64
#define T_ 300
#define V_ 25
#define F_ 64
#define TPB 5
#define M_ 125
#define TV (T_ * V_)
#define WH_ST 36            // uint32 words per Whi/Wlo row; (4g+qt) conflict-free
#define HS_ST 72
#define AT_ST 36
#define OS_ST 67
#define ALPHA 0.2f
#define NEG_INF_ -9.0e15f

// ---- smem float offsets ----
#define OFF_OS  0           // os[125][67]=8375 ; union with Whi/Wlo (dead after GEMM1)
#define OFF_WHI 0           // 72*36 u32 = 2592
#define OFF_WLO 2592        // 72*36 u32 = 2592 (ends 5184 < 8375)
#define OFF_HS  8376        // hs[132][72] = 9504
#define OFF_ATT 17880       // attm[160][36] = 5760
#define OFF_F1  23640       // 128 (also staging scratch for fold sums)
#define OFF_F2  23768       // 128
#define OFF_ADJ 23896       // 625 ints
#define SMEM_FLOATS 24521
#define SMEM_BYTES (SMEM_FLOATS * 4)   // 98084 B -> 2 CTAs/SM

__device__ __forceinline__ void split_tf32(float v, uint32_t& hi, uint32_t& lo) {
    uint32_t u = __float_as_uint(v) & 0xFFFFE000u;
    hi = u;
    lo = __float_as_uint(v - __uint_as_float(u));
}
__device__ __forceinline__ float bfres(float v) {           // residual after bf16 truncation
    return v - __uint_as_float(__float_as_uint(v) & 0xFFFF0000u);
}
__device__ __forceinline__ uint32_t packhi(float f0, float f1) {   // {bf16t(f0)|bf16t(f1)<<16}
    return __byte_perm(__float_as_uint(f0), __float_as_uint(f1), 0x7632);
}
__device__ __forceinline__ uint32_t packlo(float f0, float f1) {   // rn residual pair
    uint32_t d;
    asm("cvt.rn.bf16x2.f32 %0, %1, %2;" : "=r"(d) : "f"(bfres(f1)), "f"(bfres(f0)));
    return d;
}
__device__ __forceinline__ float elu(float v) { return (v > 0.f) ? v : (__expf(v) - 1.f); }

#define MMA_BF16(d, a, b0, b1) \
    asm volatile("mma.sync.aligned.m16n8k16.row.col.f32.bf16.bf16.f32 " \
        "{%0,%1,%2,%3}, {%4,%5,%6,%7}, {%8,%9}, {%0,%1,%2,%3};" \
        : "+f"((d)[0]), "+f"((d)[1]), "+f"((d)[2]), "+f"((d)[3]) \
        : "r"((a)[0]), "r"((a)[1]), "r"((a)[2]), "r"((a)[3]), "r"(b0), "r"(b1))

#define MMA_TF32(d, a, b0, b1) \
    asm volatile("mma.sync.aligned.m16n8k8.row.col.f32.tf32.tf32.f32 " \
        "{%0,%1,%2,%3}, {%4,%5,%6,%7}, {%8,%9}, {%0,%1,%2,%3};" \
        : "+f"((d)[0]), "+f"((d)[1]), "+f"((d)[2]), "+f"((d)[3]) \
        : "r"((a)[0]), "r"((a)[1]), "r"((a)[2]), "r"((a)[3]), "r"(b0), "r"(b1))

__global__ void __launch_bounds__(256, 2) gat_kernel(
    const float* __restrict__ x,    // (N, C, T, V)
    const int*   __restrict__ adj,  // (V, V)
    const float* __restrict__ W,    // (C, F)
    const float* __restrict__ av,   // (2F, 1)
    float*       __restrict__ out)  // (N, F, T, V)
{
    extern __shared__ float sm[];
    float*    os   = sm + OFF_OS;
    uint32_t* Whi  = (uint32_t*)(sm + OFF_WHI);
    uint32_t* Wlo  = (uint32_t*)(sm + OFF_WLO);
    float*    hs   = sm + OFF_HS;
    float*    attm = sm + OFF_ATT;
    float*    f1s  = sm + OFF_F1;
    float*    f2s  = sm + OFF_F2;
    int*      adjs = (int*)(sm + OFF_ADJ);

    const int tid = threadIdx.x;
    const int w   = tid >> 5;
    const int l   = tid & 31;
    const int g   = l >> 2;
    const int qt  = l & 3;

    const int n  = blockIdx.x / (T_ / TPB);
    const int bt = blockIdx.x % (T_ / TPB);
    const int t0 = bt * TPB;
    const float* xn   = x   + (size_t)n * C_ * TV + (size_t)t0 * V_;
    float*       outn = out + (size_t)n * F_ * TV + (size_t)t0 * V_;

    // ---- A-fragment gmem loads first (front-batched MLP) ----
    const int mA0 = 16 * w + g;          // < 120
    const bool vA1 = (mA0 + 8) < M_;
    float Ax[4][8];
    #pragma unroll
    for (int ks = 0; ks < 4; ++ks) {
        const int c0 = 16 * ks + 2 * qt;
        Ax[ks][0] = xn[c0 * TV + mA0];
        Ax[ks][1] = xn[(c0 + 1) * TV + mA0];
        Ax[ks][2] = vA1 ? xn[c0 * TV + mA0 + 8] : 0.f;
        Ax[ks][3] = vA1 ? xn[(c0 + 1) * TV + mA0 + 8] : 0.f;
        Ax[ks][4] = xn[(c0 + 8) * TV + mA0];
        Ax[ks][5] = xn[(c0 + 9) * TV + mA0];
        Ax[ks][6] = vA1 ? xn[(c0 + 8) * TV + mA0 + 8] : 0.f;
        Ax[ks][7] = vA1 ? xn[(c0 + 9) * TV + mA0 + 8] : 0.f;
    }

    // ---- staging: W presplit to packed-bf16 Whi/Wlo; fold sums; adj; zero fills ----
    for (int i = tid; i < 32 * F_; i += 256) {
        const int wc = i >> 6;           // c-pair 0..31
        const int f  = i & 63;
        const float w0 = W[(2 * wc) * F_ + f];
        const float w1 = W[(2 * wc + 1) * F_ + f];
        Whi[f * WH_ST + wc] = packhi(w0, w1);
        Wlo[f * WH_ST + wc] = packlo(w0, w1);
    }
    {   // fold sums s1(c)=sum_f W[c][f]a1[f], s2 likewise -> scratch f1s/f2s
        const int c = tid >> 2;
        const int q = tid & 3;
        const float* wr = W + c * F_ + q * 16;
        const float* a1 = av + q * 16;
        const float* a2 = av + F_ + q * 16;
        float s1 = 0.f, s2 = 0.f;
        #pragma unroll
        for (int f = 0; f < 16; ++f) {
            const float wv = wr[f];
            s1 += wv * a1[f];
            s2 += wv * a2[f];
        }
        s1 += __shfl_xor_sync(0xffffffffu, s1, 1);
        s1 += __shfl_xor_sync(0xffffffffu, s1, 2);
        s2 += __shfl_xor_sync(0xffffffffu, s2, 1);
        s2 += __shfl_xor_sync(0xffffffffu, s2, 2);
        if (q == 0) { f1s[c] = s1; f2s[c] = s2; }
    }
    for (int i = tid; i < 6 * WH_ST; i += 256) {       // B rows 66-71 zero
        Whi[66 * WH_ST + i] = 0u;
        Wlo[66 * WH_ST + i] = 0u;
    }
    for (int i = tid; i < 160 * AT_ST; i += 256) attm[i] = 0.f;
    for (int i = tid; i < 4 * HS_ST; i += 256) hs[128 * HS_ST + i] = 0.f;
    for (int i = tid; i < V_ * V_; i += 256) adjs[i] = adj[i];
    __syncthreads();

    if (tid < 32) {      // pack fold rows 64 (Wa1) / 65 (Wa2)
        const int wc = tid;
        const float s10 = f1s[2 * wc], s11 = f1s[2 * wc + 1];
        const float s20 = f2s[2 * wc], s21 = f2s[2 * wc + 1];
        Whi[64 * WH_ST + wc] = packhi(s10, s11);
        Wlo[64 * WH_ST + wc] = packlo(s10, s11);
        Whi[65 * WH_ST + wc] = packhi(s20, s21);
        Wlo[65 * WH_ST + wc] = packlo(s20, s21);
    }
    __syncthreads();

    // ---- GEMM1 (bf16 m16n8k16, 3-term): D[128][72] = x @ [W | Wa1 | Wa2 | 0]^T ----
    float D[9][4];
    #pragma unroll
    for (int nt = 0; nt < 9; ++nt)
        #pragma unroll
        for (int q = 0; q < 4; ++q) D[nt][q] = 0.f;

    #pragma unroll
    for (int ks = 0; ks < 4; ++ks) {
        uint32_t ah[4], al[4];
        ah[0] = packhi(Ax[ks][0], Ax[ks][1]);  al[0] = packlo(Ax[ks][0], Ax[ks][1]);
        ah[1] = packhi(Ax[ks][2], Ax[ks][3]);  al[1] = packlo(Ax[ks][2], Ax[ks][3]);
        ah[2] = packhi(Ax[ks][4], Ax[ks][5]);  al[2] = packlo(Ax[ks][4], Ax[ks][5]);
        ah[3] = packhi(Ax[ks][6], Ax[ks][7]);  al[3] = packlo(Ax[ks][6], Ax[ks][7]);
        const int kw = 8 * ks + qt;
        #pragma unroll
        for (int nt = 0; nt < 9; ++nt) {
            const int row = (8 * nt + g) * WH_ST;
            const uint32_t bh0 = Whi[row + kw], bh1 = Whi[row + kw + 4];
            const uint32_t bl0 = Wlo[row + kw], bl1 = Wlo[row + kw + 4];
            MMA_BF16(D[nt], ah, bh0, bh1);
            MMA_BF16(D[nt], ah, bl0, bl1);
            MMA_BF16(D[nt], al, bh0, bh1);
        }
    }

    // ---- write hs + f1/f2 from fold columns ----
    {
        const int m = 16 * w + g;
        #pragma unroll
        for (int nt = 0; nt < 8; ++nt) {
            const int cc = nt * 8 + 2 * qt;
            *(float2*)&hs[m * HS_ST + cc]       = make_float2(D[nt][0], D[nt][1]);
            *(float2*)&hs[(m + 8) * HS_ST + cc] = make_float2(D[nt][2], D[nt][3]);
        }
        if (qt == 0) {
            f1s[m]     = D[8][0];  f2s[m]     = D[8][1];
            f1s[m + 8] = D[8][2];  f2s[m + 8] = D[8][3];
        }
    }
    __syncthreads();

    // ---- masked leaky-relu + softmax -> attm (padded-row layout, 32/group) ----
    if (tid < 160) {
        const int v = tid & 31;
        if (v < V_) {
            const int gg = tid >> 5;
            const int base = gg * V_;
            const float fi = f1s[base + v];
            float e[V_];
            float mx = NEG_INF_;
            #pragma unroll
            for (int j = 0; j < V_; ++j) {
                float val = fi + f2s[base + j];
                val = (val > 0.f) ? val : ALPHA * val;
                val = (adjs[v * V_ + j] > 0) ? val : NEG_INF_;
                e[j] = val;
                mx = fmaxf(mx, val);
            }
            float s = 0.f;
            #pragma unroll
            for (int j = 0; j < V_; ++j) { const float p = __expf(e[j] - mx); e[j] = p; s += p; }
            const float inv = 1.f / s;
            #pragma unroll
            for (int j = 0; j < V_; ++j) attm[tid * AT_ST + j] = e[j] * inv;
        }
    }
    __syncthreads();

    // ---- GEMM2 (tensor tf32, R11-proven): strips of 16 padded rows ----
    const int nstrips = (w < 2) ? 2 : 1;
    for (int pass = 0; pass < nstrips; ++pass) {
        const int s = (pass == 0) ? w : (8 + w);
        const int base = V_ * (s >> 1);
        const int ra = 16 * s + g;

        float D2[8][4];
        #pragma unroll
        for (int nt = 0; nt < 8; ++nt)
            #pragma unroll
            for (int q = 0; q < 4; ++q) D2[nt][q] = 0.f;

        #pragma unroll
        for (int ks = 0; ks < 4; ++ks) {
            const int k0 = 8 * ks + qt;
            uint32_t ah[4], al[4];
            split_tf32(attm[ra * AT_ST + k0],           ah[0], al[0]);
            split_tf32(attm[(ra + 8) * AT_ST + k0],     ah[1], al[1]);
            split_tf32(attm[ra * AT_ST + k0 + 4],       ah[2], al[2]);
            split_tf32(attm[(ra + 8) * AT_ST + k0 + 4], ah[3], al[3]);
            #pragma unroll
            for (int nt = 0; nt < 8; ++nt) {
                uint32_t bh0, bl0, bh1, bl1;
                split_tf32(hs[(base + k0) * HS_ST + 8 * nt + g],     bh0, bl0);
                split_tf32(hs[(base + k0 + 4) * HS_ST + 8 * nt + g], bh1, bl1);
                MMA_TF32(D2[nt], ah, bh0, bh1);
                MMA_TF32(D2[nt], ah, bl0, bl1);
                MMA_TF32(D2[nt], al, bh0, bh1);
            }
        }

        const int v0 = ra & 31;
        const int v1 = (ra + 8) & 31;
        const int m0r = base + v0;
        const int m1r = base + v1;
        const bool st1 = (v1 < V_);
        #pragma unroll
        for (int nt = 0; nt < 8; ++nt) {
            const int cc = nt * 8 + 2 * qt;
            os[m0r * OS_ST + cc]     = elu(D2[nt][0]);
            os[m0r * OS_ST + cc + 1] = elu(D2[nt][1]);
            if (st1) {
                os[m1r * OS_ST + cc]     = elu(D2[nt][2]);
                os[m1r * OS_ST + cc + 1] = elu(D2[nt][3]);
            }
        }
    }
    __syncthreads();

    // ---- store: out[n][f][t0*25 + m], 125 contiguous floats per f ----
    for (int f = w; f < F_; f += 8) {
        for (int mm = l; mm < M_; mm += 32)
            outn[f * TV + mm] = os[mm * OS_ST + f];
    }
}

extern "C" void kernel_launch(void* const* d_in, const int* in_sizes, int n_in,
                              void* d_out, int out_size)
{
    const float* x   = (const float*)d_in[0];
    const int*   adj = (const int*)  d_in[1];
    const float* W   = (const float*)d_in[2];
    const float* a   = (const float*)d_in[3];
    float* out = (float*)d_out;

    cudaFuncSetAttribute(gat_kernel, cudaFuncAttributeMaxDynamicSharedMemorySize, SMEM_BYTES);
    dim3 grid(N_ * (T_ / TPB));
    gat_kernel<<<grid, 256, SMEM_BYTES>>>(x, adj, W, a, out);
}

// round 13
// speedup vs baseline: 2.1098x; 1.0036x over previous
#include <cuda_runtime.h>
#include <cstdint>

#define N_ 64
#define C_ 64
#define T_ 300
#define V_ 25
#define F_ 64
#define TPB 5
#define M_ 125
#define TV (T_ * V_)
#define WH_ST 36            // uint32 words per Whi/Wlo row; (4g+qt) conflict-free
#define HS_ST 72
#define AT_ST 36
#define OS_ST 67
#define ALPHA 0.2f
#define NEG_INF_ -9.0e15f

// ---- smem float offsets ----
#define OFF_OS  0           // os[125][67]=8375 ; union with Whi/Wlo (dead after GEMM1)
#define OFF_WHI 0           // 72*36 u32 = 2592
#define OFF_WLO 2592        // 72*36 u32 = 2592 (ends 5184 < 8375)
#define OFF_HS  8376        // hs[132][72] = 9504
#define OFF_ATT 17880       // attm[160][36] = 5760
#define OFF_F1  23640       // 128 (also staging scratch for fold sums)
#define OFF_F2  23768       // 128
#define OFF_ADJ 23896       // 625 ints
#define SMEM_FLOATS 24521
#define SMEM_BYTES (SMEM_FLOATS * 4)   // 98084 B -> 2 CTAs/SM

__device__ __forceinline__ void split_tf32(float v, uint32_t& hi, uint32_t& lo) {
    uint32_t u = __float_as_uint(v) & 0xFFFFE000u;
    hi = u;
    lo = __float_as_uint(v - __uint_as_float(u));
}
__device__ __forceinline__ float bfres(float v) {           // residual after bf16 truncation
    return v - __uint_as_float(__float_as_uint(v) & 0xFFFF0000u);
}
__device__ __forceinline__ uint32_t packhi(float f0, float f1) {   // {bf16t(f0)|bf16t(f1)<<16}
    return __byte_perm(__float_as_uint(f0), __float_as_uint(f1), 0x7632);
}
__device__ __forceinline__ uint32_t packlo(float f0, float f1) {   // rn residual pair
    uint32_t d;
    asm("cvt.rn.bf16x2.f32 %0, %1, %2;" : "=r"(d) : "f"(bfres(f1)), "f"(bfres(f0)));
    return d;
}
__device__ __forceinline__ float elu(float v) { return (v > 0.f) ? v : (__expf(v) - 1.f); }

#define MMA_BF16(d, a, b0, b1) \
    asm volatile("mma.sync.aligned.m16n8k16.row.col.f32.bf16.bf16.f32 " \
        "{%0,%1,%2,%3}, {%4,%5,%6,%7}, {%8,%9}, {%0,%1,%2,%3};" \
        : "+f"((d)[0]), "+f"((d)[1]), "+f"((d)[2]), "+f"((d)[3]) \
        : "r"((a)[0]), "r"((a)[1]), "r"((a)[2]), "r"((a)[3]), "r"(b0), "r"(b1))

#define MMA_TF32(d, a, b0, b1) \
    asm volatile("mma.sync.aligned.m16n8k8.row.col.f32.tf32.tf32.f32 " \
        "{%0,%1,%2,%3}, {%4,%5,%6,%7}, {%8,%9}, {%0,%1,%2,%3};" \
        : "+f"((d)[0]), "+f"((d)[1]), "+f"((d)[2]), "+f"((d)[3]) \
        : "r"((a)[0]), "r"((a)[1]), "r"((a)[2]), "r"((a)[3]), "r"(b0), "r"(b1))

__global__ void __launch_bounds__(256, 2) gat_kernel(
    const float* __restrict__ x,    // (N, C, T, V)
    const int*   __restrict__ adj,  // (V, V)
    const float* __restrict__ W,    // (C, F)
    const float* __restrict__ av,   // (2F, 1)
    float*       __restrict__ out)  // (N, F, T, V)
{
    extern __shared__ float sm[];
    float*    os   = sm + OFF_OS;
    uint32_t* Whi  = (uint32_t*)(sm + OFF_WHI);
    uint32_t* Wlo  = (uint32_t*)(sm + OFF_WLO);
    float*    hs   = sm + OFF_HS;
    float*    attm = sm + OFF_ATT;
    float*    f1s  = sm + OFF_F1;
    float*    f2s  = sm + OFF_F2;
    int*      adjs = (int*)(sm + OFF_ADJ);

    const int tid = threadIdx.x;
    const int w   = tid >> 5;
    const int l   = tid & 31;
    const int g   = l >> 2;
    const int qt  = l & 3;

    const int n  = blockIdx.x / (T_ / TPB);
    const int bt = blockIdx.x % (T_ / TPB);
    const int t0 = bt * TPB;
    const float* xn   = x   + (size_t)n * C_ * TV + (size_t)t0 * V_;
    float*       outn = out + (size_t)n * F_ * TV + (size_t)t0 * V_;

    // ---- A-fragment gmem loads first (front-batched MLP) ----
    const int mA0 = 16 * w + g;          // < 120
    const bool vA1 = (mA0 + 8) < M_;
    float Ax[4][8];
    #pragma unroll
    for (int ks = 0; ks < 4; ++ks) {
        const int c0 = 16 * ks + 2 * qt;
        Ax[ks][0] = xn[c0 * TV + mA0];
        Ax[ks][1] = xn[(c0 + 1) * TV + mA0];
        Ax[ks][2] = vA1 ? xn[c0 * TV + mA0 + 8] : 0.f;
        Ax[ks][3] = vA1 ? xn[(c0 + 1) * TV + mA0 + 8] : 0.f;
        Ax[ks][4] = xn[(c0 + 8) * TV + mA0];
        Ax[ks][5] = xn[(c0 + 9) * TV + mA0];
        Ax[ks][6] = vA1 ? xn[(c0 + 8) * TV + mA0 + 8] : 0.f;
        Ax[ks][7] = vA1 ? xn[(c0 + 9) * TV + mA0 + 8] : 0.f;
    }

    // ---- staging: W presplit to packed-bf16 Whi/Wlo; fold sums; adj; zero fills ----
    for (int i = tid; i < 32 * F_; i += 256) {
        const int wc = i >> 6;           // c-pair 0..31
        const int f  = i & 63;
        const float w0 = W[(2 * wc) * F_ + f];
        const float w1 = W[(2 * wc + 1) * F_ + f];
        Whi[f * WH_ST + wc] = packhi(w0, w1);
        Wlo[f * WH_ST + wc] = packlo(w0, w1);
    }
    {   // fold sums s1(c)=sum_f W[c][f]a1[f], s2 likewise -> scratch f1s/f2s
        const int c = tid >> 2;
        const int q = tid & 3;
        const float* wr = W + c * F_ + q * 16;
        const float* a1 = av + q * 16;
        const float* a2 = av + F_ + q * 16;
        float s1 = 0.f, s2 = 0.f;
        #pragma unroll
        for (int f = 0; f < 16; ++f) {
            const float wv = wr[f];
            s1 += wv * a1[f];
            s2 += wv * a2[f];
        }
        s1 += __shfl_xor_sync(0xffffffffu, s1, 1);
        s1 += __shfl_xor_sync(0xffffffffu, s1, 2);
        s2 += __shfl_xor_sync(0xffffffffu, s2, 1);
        s2 += __shfl_xor_sync(0xffffffffu, s2, 2);
        if (q == 0) { f1s[c] = s1; f2s[c] = s2; }
    }
    for (int i = tid; i < 6 * WH_ST; i += 256) {       // B rows 66-71 zero
        Whi[66 * WH_ST + i] = 0u;
        Wlo[66 * WH_ST + i] = 0u;
    }
    for (int i = tid; i < 160 * AT_ST; i += 256) attm[i] = 0.f;
    for (int i = tid; i < 4 * HS_ST; i += 256) hs[128 * HS_ST + i] = 0.f;
    for (int i = tid; i < V_ * V_; i += 256) adjs[i] = adj[i];
    __syncthreads();

    if (tid < 32) {      // pack fold rows 64 (Wa1) / 65 (Wa2)
        const int wc = tid;
        const float s10 = f1s[2 * wc], s11 = f1s[2 * wc + 1];
        const float s20 = f2s[2 * wc], s21 = f2s[2 * wc + 1];
        Whi[64 * WH_ST + wc] = packhi(s10, s11);
        Wlo[64 * WH_ST + wc] = packlo(s10, s11);
        Whi[65 * WH_ST + wc] = packhi(s20, s21);
        Wlo[65 * WH_ST + wc] = packlo(s20, s21);
    }
    __syncthreads();

    // ---- GEMM1 (bf16 m16n8k16, 3-term): D[128][72] = x @ [W | Wa1 | Wa2 | 0]^T ----
    float D[9][4];
    #pragma unroll
    for (int nt = 0; nt < 9; ++nt)
        #pragma unroll
        for (int q = 0; q < 4; ++q) D[nt][q] = 0.f;

    #pragma unroll
    for (int ks = 0; ks < 4; ++ks) {
        uint32_t ah[4], al[4];
        ah[0] = packhi(Ax[ks][0], Ax[ks][1]);  al[0] = packlo(Ax[ks][0], Ax[ks][1]);
        ah[1] = packhi(Ax[ks][2], Ax[ks][3]);  al[1] = packlo(Ax[ks][2], Ax[ks][3]);
        ah[2] = packhi(Ax[ks][4], Ax[ks][5]);  al[2] = packlo(Ax[ks][4], Ax[ks][5]);
        ah[3] = packhi(Ax[ks][6], Ax[ks][7]);  al[3] = packlo(Ax[ks][6], Ax[ks][7]);
        const int kw = 8 * ks + qt;
        #pragma unroll
        for (int nt = 0; nt < 9; ++nt) {
            const int row = (8 * nt + g) * WH_ST;
            const uint32_t bh0 = Whi[row + kw], bh1 = Whi[row + kw + 4];
            const uint32_t bl0 = Wlo[row + kw], bl1 = Wlo[row + kw + 4];
            MMA_BF16(D[nt], ah, bh0, bh1);
            MMA_BF16(D[nt], ah, bl0, bl1);
            MMA_BF16(D[nt], al, bh0, bh1);
        }
    }

    // ---- write hs + f1/f2 from fold columns ----
    {
        const int m = 16 * w + g;
        #pragma unroll
        for (int nt = 0; nt < 8; ++nt) {
            const int cc = nt * 8 + 2 * qt;
            *(float2*)&hs[m * HS_ST + cc]       = make_float2(D[nt][0], D[nt][1]);
            *(float2*)&hs[(m + 8) * HS_ST + cc] = make_float2(D[nt][2], D[nt][3]);
        }
        if (qt == 0) {
            f1s[m]     = D[8][0];  f2s[m]     = D[8][1];
            f1s[m + 8] = D[8][2];  f2s[m + 8] = D[8][3];
        }
    }
    __syncthreads();

    // ---- masked leaky-relu + softmax -> attm (padded-row layout, 32/group) ----
    if (tid < 160) {
        const int v = tid & 31;
        if (v < V_) {
            const int gg = tid >> 5;
            const int base = gg * V_;
            const float fi = f1s[base + v];
            float e[V_];
            float mx = NEG_INF_;
            #pragma unroll
            for (int j = 0; j < V_; ++j) {
                float val = fi + f2s[base + j];
                val = (val > 0.f) ? val : ALPHA * val;
                val = (adjs[v * V_ + j] > 0) ? val : NEG_INF_;
                e[j] = val;
                mx = fmaxf(mx, val);
            }
            float s = 0.f;
            #pragma unroll
            for (int j = 0; j < V_; ++j) { const float p = __expf(e[j] - mx); e[j] = p; s += p; }
            const float inv = 1.f / s;
            #pragma unroll
            for (int j = 0; j < V_; ++j) attm[tid * AT_ST + j] = e[j] * inv;
        }
    }
    __syncthreads();

    // ---- GEMM2 (tensor tf32, R11-proven): strips of 16 padded rows ----
    const int nstrips = (w < 2) ? 2 : 1;
    for (int pass = 0; pass < nstrips; ++pass) {
        const int s = (pass == 0) ? w : (8 + w);
        const int base = V_ * (s >> 1);
        const int ra = 16 * s + g;

        float D2[8][4];
        #pragma unroll
        for (int nt = 0; nt < 8; ++nt)
            #pragma unroll
            for (int q = 0; q < 4; ++q) D2[nt][q] = 0.f;

        #pragma unroll
        for (int ks = 0; ks < 4; ++ks) {
            const int k0 = 8 * ks + qt;
            uint32_t ah[4], al[4];
            split_tf32(attm[ra * AT_ST + k0],           ah[0], al[0]);
            split_tf32(attm[(ra + 8) * AT_ST + k0],     ah[1], al[1]);
            split_tf32(attm[ra * AT_ST + k0 + 4],       ah[2], al[2]);
            split_tf32(attm[(ra + 8) * AT_ST + k0 + 4], ah[3], al[3]);
            #pragma unroll
            for (int nt = 0; nt < 8; ++nt) {
                uint32_t bh0, bl0, bh1, bl1;
                split_tf32(hs[(base + k0) * HS_ST + 8 * nt + g],     bh0, bl0);
                split_tf32(hs[(base + k0 + 4) * HS_ST + 8 * nt + g], bh1, bl1);
                MMA_TF32(D2[nt], ah, bh0, bh1);
                MMA_TF32(D2[nt], ah, bl0, bl1);
                MMA_TF32(D2[nt], al, bh0, bh1);
            }
        }

        const int v0 = ra & 31;
        const int v1 = (ra + 8) & 31;
        const int m0r = base + v0;
        const int m1r = base + v1;
        const bool st1 = (v1 < V_);
        #pragma unroll
        for (int nt = 0; nt < 8; ++nt) {
            const int cc = nt * 8 + 2 * qt;
            os[m0r * OS_ST + cc]     = elu(D2[nt][0]);
            os[m0r * OS_ST + cc + 1] = elu(D2[nt][1]);
            if (st1) {
                os[m1r * OS_ST + cc]     = elu(D2[nt][2]);
                os[m1r * OS_ST + cc + 1] = elu(D2[nt][3]);
            }
        }
    }
    __syncthreads();

    // ---- store: out[n][f][t0*25 + m], 125 contiguous floats per f ----
    for (int f = w; f < F_; f += 8) {
        for (int mm = l; mm < M_; mm += 32)
            outn[f * TV + mm] = os[mm * OS_ST + f];
    }
}

extern "C" void kernel_launch(void* const* d_in, const int* in_sizes, int n_in,
                              void* d_out, int out_size)
{
    const float* x   = (const float*)d_in[0];
    const int*   adj = (const int*)  d_in[1];
    const float* W   = (const float*)d_in[2];
    const float* a   = (const float*)d_in[3];
    float* out = (float*)d_out;

    cudaFuncSetAttribute(gat_kernel, cudaFuncAttributeMaxDynamicSharedMemorySize, SMEM_BYTES);
    dim3 grid(N_ * (T_ / TPB));
    gat_kernel<<<grid, 256, SMEM_BYTES>>>(x, adj, W, a, out);
}